// round 15
// baseline (speedup 1.0000x reference)
#include <cuda_runtime.h>
#include <cuda_fp16.h>
#include <math.h>
#include <stdint.h>

#define N_NODES 100000
#define N_EDGES 1600000
#define DIN 512
#define DH 128
#define DOUT 40
#define H2_STRIDE 64                       // padded h2 row (halves) -> 128 B lines
#define TOT_EDGES (N_EDGES + N_NODES)

// ---------------- scratch (device globals; no runtime allocation) -------------
__device__ int      g_degc[N_NODES + 1];  // [i]=deg(+1 after alloc); [N_NODES]=cursor
__device__ int      g_off[N_NODES];       // bucket start (unordered)
__device__ int      g_cur[N_NODES];
__device__ float    g_dinv[N_NODES];
__device__ __align__(16) uint32_t g_csr4[TOT_EDGES];            // (w15 << 17) | src17
__device__ __align__(16) __half g_h1h[(size_t)N_NODES * DH];    // X @ W1 (fp16)
__device__ __align__(16) __half g_a1h[(size_t)N_NODES * DH];    // relu(agg+b1) (fp16)
__device__ __align__(16) __half g_h2h[(size_t)N_NODES * H2_STRIDE]; // a1 @ W2 (fp16, padded)
__device__ __align__(16) __half g_w1hf[(size_t)DH * DIN];       // W1 fp16, B-fragment layout
__device__ __align__(16) __half g_w2hf[(size_t)(DH / 16) * DOUT * 16]; // W2 fp16 B-frag

// ---------------- helpers -------------------------------------------------------
__device__ __forceinline__ uint32_t smem_u32(const void* p) {
    uint32_t a;
    asm("{ .reg .u64 t; cvta.to.shared.u64 t, %1; cvt.u32.u64 %0, t; }" : "=r"(a) : "l"(p));
    return a;
}

__device__ __forceinline__ uint32_t packh2(float2 v) {
    __half2 h = __floats2half2_rn(v.x, v.y);
    return *reinterpret_cast<uint32_t*>(&h);
}

// decode packed csr entry -> (src, w)
__device__ __forceinline__ void csr_decode(uint32_t e, int& s, float& w) {
    s = (int)(e & 0x1FFFFu);
    unsigned short hb = (unsigned short)(e >> 17);   // fp16 bits, sign=0
    w = __half2float(__ushort_as_half(hb));
}

__device__ __forceinline__ void mma_f16(float* c, const uint32_t* a, uint32_t b0, uint32_t b1) {
    asm volatile(
        "mma.sync.aligned.m16n8k16.row.col.f32.f16.f16.f32 "
        "{%0,%1,%2,%3}, {%4,%5,%6,%7}, {%8,%9}, {%0,%1,%2,%3};"
        : "+f"(c[0]), "+f"(c[1]), "+f"(c[2]), "+f"(c[3])
        : "r"(a[0]), "r"(a[1]), "r"(a[2]), "r"(a[3]), "r"(b0), "r"(b1));
}

// ---------------- histogram (deg zeroed by one memset; self-loop added in alloc) -
__global__ void hist_kernel(const int* __restrict__ dst) {
    int e = blockIdx.x * blockDim.x + threadIdx.x;
    if (e < N_EDGES) atomicAdd(&g_degc[dst[e]], 1);
}

// ---------------- W precompute (W1 + W2, both fp16 B-fragment layout) ------------
__global__ void wt_kernel(const float* __restrict__ W1, const float* __restrict__ W2) {
    if (blockIdx.y < 16) {
        const int n0 = blockIdx.x * 32, k0 = blockIdx.y * 32;
        const int n = n0 + threadIdx.x, k = k0 + threadIdx.y;
        float v = W1[(size_t)k * DH + n];
        int c = k >> 5, kt = (k >> 4) & 1, q = k & 15;
        size_t slot = ((size_t)(c * 2 + kt) * 128 + n) * 16
                      + ((q & 7) >> 1) * 4 + ((q >> 3) & 1) * 2 + (q & 1);
        g_w1hf[slot] = __float2half_rn(v);
    } else if (blockIdx.x == 0) {
        int tid = threadIdx.y * 32 + threadIdx.x;
        for (int idx = tid; idx < DH * DOUT; idx += 1024) {
            int k = idx / DOUT, n = idx % DOUT;
            int kt = k >> 4, q = k & 15;
            size_t slot = ((size_t)kt * DOUT + n) * 16
                          + ((q & 7) >> 1) * 4 + ((q >> 3) & 1) * 2 + (q & 1);
            g_w2hf[slot] = __float2half_rn(W2[idx]);
        }
    }
}

// ---------------- bucket allocation (order-free CSR); writes total degree back ---
__global__ void alloc_kernel() {
    int i = blockIdx.x * blockDim.x + threadIdx.x;
    if (i >= N_NODES) return;
    int v = g_degc[i] + 1;                // + self-loop
    int off = atomicAdd(&g_degc[N_NODES], v);
    g_degc[i] = v;                        // store total for agg loops
    g_off[i] = off;
    g_cur[i] = off;
    g_dinv[i] = rsqrtf((float)v);
}

__global__ void scatter_kernel(const int* __restrict__ src, const int* __restrict__ dst) {
    int e = blockIdx.x * blockDim.x + threadIdx.x;
    if (e >= TOT_EDGES) return;
    int s, d;
    if (e < N_EDGES) { s = src[e]; d = dst[e]; }
    else             { s = d = e - N_EDGES; }
    int pos = atomicAdd(&g_cur[d], 1);
    float w = g_dinv[s] * g_dinv[d];
    unsigned short hb = __half_as_ushort(__float2half_rn(w));   // sign bit = 0
    g_csr4[pos] = ((uint32_t)hb << 17) | (uint32_t)s;
}

// ---------------- GEMM1: h1 = X @ W1, fp16 MMA, M-tile 64 (3 CTAs/SM) ------------
#define NCH 16
#define STAGES 3
#define TILE_M 64
#define A_STRIDE 40                            // A floats per row (pad 32 -> 40)
#define A_TILE_F (TILE_M * A_STRIDE)           // 2560 floats = 10240 B
#define B_TILE_H 4096                          // fragment-layout fp16 tile (8192 B)
#define STAGE_B (A_TILE_F * 4 + B_TILE_H * 2)  // 18432 B
#define G1_SMEM (STAGES * STAGE_B)             // 55296 B (3 CTAs/SM)

__global__ __launch_bounds__(256, 3) void gemm1_f16_kernel(const float* __restrict__ X) {
    extern __shared__ float s1[];
    const uint32_t sbase = smem_u32(s1);
    const int tid  = threadIdx.x;
    const int row0 = blockIdx.x * TILE_M;

    const int ldrow = tid >> 3;                // 0..31
    const int ldkq  = tid & 7;

    auto issue = [&](int c) {
        const int s = c % STAGES;
        const uint32_t sa = sbase + s * STAGE_B;
        const uint32_t sb = sa + A_TILE_F * 4;
        const int k0 = c * 32;
        #pragma unroll
        for (int j = 0; j < 2; j++) {          // 64 rows over 256 thr (8/row)
            const int row = ldrow + j * 32;
            const int gr  = row0 + row;
            const int zn  = (gr < N_NODES) ? 16 : 0;
            const float* ga = X + (size_t)(gr < N_NODES ? gr : 0) * DIN + k0 + ldkq * 4;
            asm volatile("cp.async.cg.shared.global [%0], [%1], 16, %2;"
                         :: "r"(sa + row * (A_STRIDE * 4) + ldkq * 16), "l"(ga), "r"(zn));
        }
        const __half* gb = g_w1hf + (size_t)c * B_TILE_H;
        asm volatile("cp.async.cg.shared.global [%0], [%1], 16;"
                     :: "r"(sb + tid * 32), "l"(reinterpret_cast<const char*>(gb) + tid * 32));
        asm volatile("cp.async.cg.shared.global [%0], [%1], 16;"
                     :: "r"(sb + tid * 32 + 16),
                        "l"(reinterpret_cast<const char*>(gb) + tid * 32 + 16));
    };

    issue(0);
    asm volatile("cp.async.commit_group;" ::: "memory");
    issue(1);
    asm volatile("cp.async.commit_group;" ::: "memory");

    const int wid = tid >> 5, lane = tid & 31;
    const int wm = wid & 3, wn = wid >> 2;     // 4 M-groups x 2 N-halves
    const int g = lane >> 2, tg = lane & 3;

    float acc[8][4];                           // M16 x 8 N8-tiles
    #pragma unroll
    for (int b = 0; b < 8; b++)
        #pragma unroll
        for (int c = 0; c < 4; c++) acc[b][c] = 0.f;

    #pragma unroll 1
    for (int c = 0; c < NCH; c++) {
        asm volatile("cp.async.wait_group 1;" ::: "memory");
        __syncthreads();
        if (c + STAGES - 1 < NCH) issue(c + STAGES - 1);
        asm volatile("cp.async.commit_group;" ::: "memory");

        const float*  sA = s1 + (size_t)(c % STAGES) * (STAGE_B / 4);
        const __half* sB = reinterpret_cast<const __half*>(sA + A_TILE_F);

        #pragma unroll
        for (int kt = 0; kt < 2; kt++) {
            uint32_t a[4];
            {
                const float2* pa = reinterpret_cast<const float2*>(
                    sA + (wm * 16 + g) * A_STRIDE + kt * 16 + tg * 2);
                const float2* pa8 = pa + 4 * A_STRIDE;   // +8 rows
                float2 v00 = pa[0],  v10 = pa[4];
                float2 v01 = pa8[0], v11 = pa8[4];
                a[0] = packh2(v00);
                a[1] = packh2(v01);
                a[2] = packh2(v10);
                a[3] = packh2(v11);
            }
            #pragma unroll
            for (int nt = 0; nt < 8; nt++) {
                const uint2 b = *reinterpret_cast<const uint2*>(
                    sB + (size_t)kt * 2048 + (wn * 64 + nt * 8 + g) * 16 + tg * 4);
                mma_f16(acc[nt], a, b.x, b.y);
            }
        }
    }

    // epilogue -> fp16
    int r0 = row0 + wm * 16 + g;
    #pragma unroll
    for (int nt = 0; nt < 8; nt++) {
        int colb = wn * 64 + nt * 8 + tg * 2;
        if (r0 < N_NODES)
            *reinterpret_cast<__half2*>(g_h1h + (size_t)r0 * DH + colb) =
                __floats2half2_rn(acc[nt][0], acc[nt][1]);
        if (r0 + 8 < N_NODES)
            *reinterpret_cast<__half2*>(g_h1h + (size_t)(r0 + 8) * DH + colb) =
                __floats2half2_rn(acc[nt][2], acc[nt][3]);
    }
}

// ---------------- Agg1: a1 = relu(A_hat @ h1 + b1), warp per node ----------------
__global__ void agg1_kernel(const float* __restrict__ b1) {
    int gw = (blockIdx.x * blockDim.x + threadIdx.x) >> 5;
    int lane = threadIdx.x & 31;
    if (gw >= N_NODES) return;
    int beg = g_off[gw], end = beg + g_degc[gw];
    float4 acc = make_float4(0.f, 0.f, 0.f, 0.f);
    for (int p = beg; p < end; ++p) {
        int s; float w;
        csr_decode(g_csr4[p], s, w);
        uint2 hv = __ldcg(reinterpret_cast<const uint2*>(g_h1h + (size_t)s * DH) + lane);
        float2 f0 = __half22float2(*reinterpret_cast<__half2*>(&hv.x));
        float2 f1 = __half22float2(*reinterpret_cast<__half2*>(&hv.y));
        acc.x += w * f0.x; acc.y += w * f0.y; acc.z += w * f1.x; acc.w += w * f1.y;
    }
    float4 bv = *reinterpret_cast<const float4*>(b1 + lane * 4);
    __half2 o0 = __floats2half2_rn(fmaxf(acc.x + bv.x, 0.f), fmaxf(acc.y + bv.y, 0.f));
    __half2 o1 = __floats2half2_rn(fmaxf(acc.z + bv.z, 0.f), fmaxf(acc.w + bv.w, 0.f));
    uint2 st;
    st.x = *reinterpret_cast<uint32_t*>(&o0);
    st.y = *reinterpret_cast<uint32_t*>(&o1);
    *(reinterpret_cast<uint2*>(g_a1h + (size_t)gw * DH) + lane) = st;
}

// ---------------- GEMM2: h2 = a1 @ W2 via fp16 MMA (m16n8k16) --------------------
#define G2A_STRIDE_H 136
#define G2_SMEM (128 * G2A_STRIDE_H * 2 + (DH / 16) * DOUT * 16 * 2)
__global__ __launch_bounds__(128) void gemm2_f16_kernel() {
    extern __shared__ __half s2h[];
    __half* sA = s2h;                              // [128][136]
    __half* sB = s2h + 128 * G2A_STRIDE_H;         // fragment layout
    const uint32_t* sA32 = reinterpret_cast<const uint32_t*>(sA);
    const int tid  = threadIdx.x;
    const int row0 = blockIdx.x * 128;

    #pragma unroll
    for (int i = 0; i < 32; i++) {
        int idx = tid + i * 128, row = idx >> 5, q = idx & 31;
        int gr = row0 + row;
        uint2 hv = make_uint2(0u, 0u);
        if (gr < N_NODES)
            hv = __ldcs(reinterpret_cast<const uint2*>(g_a1h + (size_t)gr * DH) + q);
        *reinterpret_cast<uint2*>(sA + row * G2A_STRIDE_H + q * 4) = hv;
    }
    #pragma unroll
    for (int i = 0; i < 5; i++) {
        int idx = tid + i * 128;
        *reinterpret_cast<uint4*>(sB + idx * 8) =
            *reinterpret_cast<const uint4*>(g_w2hf + idx * 8);
    }
    __syncthreads();

    const int wid = tid >> 5, lane = tid & 31;
    const int g = lane >> 2, tg = lane & 3;

    float acc[2][5][4];
    #pragma unroll
    for (int a = 0; a < 2; a++)
        #pragma unroll
        for (int b = 0; b < 5; b++)
            #pragma unroll
            for (int c = 0; c < 4; c++) acc[a][b][c] = 0.f;

    #pragma unroll
    for (int kt = 0; kt < DH / 16; kt++) {
        uint32_t a[2][4];
        #pragma unroll
        for (int mt = 0; mt < 2; mt++) {
            int base = (wid * 32 + mt * 16 + g) * (G2A_STRIDE_H / 2) + kt * 8 + tg;
            a[mt][0] = sA32[base];
            a[mt][1] = sA32[base + 8 * (G2A_STRIDE_H / 2)];
            a[mt][2] = sA32[base + 4];
            a[mt][3] = sA32[base + 8 * (G2A_STRIDE_H / 2) + 4];
        }
        #pragma unroll
        for (int nt = 0; nt < 5; nt++) {
            const uint2 b = *reinterpret_cast<const uint2*>(
                sB + ((size_t)kt * DOUT + nt * 8 + g) * 16 + tg * 4);
            mma_f16(acc[0][nt], a[0], b.x, b.y);
            mma_f16(acc[1][nt], a[1], b.x, b.y);
        }
    }

    #pragma unroll
    for (int mt = 0; mt < 2; mt++) {
        int r0 = row0 + wid * 32 + mt * 16 + g;
        #pragma unroll
        for (int nt = 0; nt < 5; nt++) {
            int colb = nt * 8 + tg * 2;
            if (r0 < N_NODES)
                *reinterpret_cast<__half2*>(g_h2h + (size_t)r0 * H2_STRIDE + colb) =
                    __floats2half2_rn(acc[mt][nt][0], acc[mt][nt][1]);
            if (r0 + 8 < N_NODES)
                *reinterpret_cast<__half2*>(g_h2h + (size_t)(r0 + 8) * H2_STRIDE + colb) =
                    __floats2half2_rn(acc[mt][nt][2], acc[mt][nt][3]);
        }
    }
}

// ---------------- Agg2 + b2 + log_softmax fused, warp per node -------------------
__device__ __forceinline__ void stcs2(float* p, float2 v) {
    asm volatile("st.global.cs.v2.f32 [%0], {%1, %2};" :: "l"(p), "f"(v.x), "f"(v.y)
                 : "memory");
}

__global__ void agg2_lsm_kernel(const float* __restrict__ b2, float* __restrict__ out,
                                int do_lsm) {
    int gw = (blockIdx.x * blockDim.x + threadIdx.x) >> 5;
    int lane = threadIdx.x & 31;
    if (gw >= N_NODES) return;
    int beg = g_off[gw], end = beg + g_degc[gw];
    const bool act = lane < (DOUT / 2);
    float acc0 = 0.f, acc1 = 0.f;
    for (int p = beg; p < end; ++p) {
        int s; float w;
        csr_decode(g_csr4[p], s, w);
        if (act) {
            uint32_t hv = __ldcg(reinterpret_cast<const uint32_t*>(
                g_h2h + (size_t)s * H2_STRIDE) + lane);
            float2 f = __half22float2(*reinterpret_cast<__half2*>(&hv));
            acc0 += w * f.x;
            acc1 += w * f.y;
        }
    }
    if (act) {
        acc0 += b2[lane * 2];
        acc1 += b2[lane * 2 + 1];
        stcs2(out + (size_t)gw * DOUT + lane * 2, make_float2(acc0, acc1));
    }
    if (do_lsm) {
        float m = act ? fmaxf(acc0, acc1) : -INFINITY;
        #pragma unroll
        for (int o = 16; o > 0; o >>= 1) m = fmaxf(m, __shfl_xor_sync(0xffffffffu, m, o));
        float e = act ? (expf(acc0 - m) + expf(acc1 - m)) : 0.f;
        #pragma unroll
        for (int o = 16; o > 0; o >>= 1) e += __shfl_xor_sync(0xffffffffu, e, o);
        float lse = m + logf(e);
        if (act) {
            float* lrow = out + (size_t)N_NODES * DOUT + (size_t)gw * DOUT;
            stcs2(lrow + lane * 2, make_float2(acc0 - lse, acc1 - lse));
        }
    }
}

// ---------------- launch --------------------------------------------------------
// chain A (default): wt -> gemm1
// chain B (side):    memset(degc incl cursor) -> hist -> alloc -> scatter
// join -> agg1 -> gemm2 -> agg2_lsm
extern "C" void kernel_launch(void* const* d_in, const int* in_sizes, int n_in,
                              void* d_out, int out_size) {
    const float* x   = (const float*)d_in[0];
    const int*   ei  = (const int*)  d_in[1];   // [2,E] row-major
    const float* W1  = (const float*)d_in[2];
    const float* b1  = (const float*)d_in[3];
    const float* W2  = (const float*)d_in[4];
    const float* b2  = (const float*)d_in[5];
    float* out = (float*)d_out;

    const int* src = ei;
    const int* dst = ei + N_EDGES;

    cudaFuncSetAttribute(gemm1_f16_kernel, cudaFuncAttributeMaxDynamicSharedMemorySize,
                         G1_SMEM);
    cudaFuncSetAttribute(gemm2_f16_kernel, cudaFuncAttributeMaxDynamicSharedMemorySize,
                         G2_SMEM);

    void* degcPtr; cudaGetSymbolAddress(&degcPtr, g_degc);

    cudaStream_t sB;
    cudaStreamCreateWithFlags(&sB, cudaStreamNonBlocking);
    cudaEvent_t evFork, evJoin;
    cudaEventCreateWithFlags(&evFork, cudaEventDisableTiming);
    cudaEventCreateWithFlags(&evJoin, cudaEventDisableTiming);

    cudaEventRecord(evFork, 0);
    cudaStreamWaitEvent(sB, evFork, 0);

    cudaMemsetAsync(degcPtr, 0, (N_NODES + 1) * sizeof(int), sB);

    // kernel submission order: wt(1), hist(2), alloc(3), gemm1(4 <- profile), scatter(5)
    wt_kernel<<<dim3(4, 17), dim3(32, 32)>>>(W1, W2);                      // 1 (A)
    hist_kernel<<<(N_EDGES + 255) / 256, 256, 0, sB>>>(dst);               // 2 (B)
    alloc_kernel<<<(N_NODES + 255) / 256, 256, 0, sB>>>();                 // 3 (B)
    gemm1_f16_kernel<<<(N_NODES + TILE_M - 1) / TILE_M, 256, G1_SMEM>>>(x); // 4 (A)
    scatter_kernel<<<(TOT_EDGES + 255) / 256, 256, 0, sB>>>(src, dst);     // 5 (B)

    cudaEventRecord(evJoin, sB);
    cudaStreamWaitEvent(0, evJoin, 0);

    agg1_kernel<<<(N_NODES * 32 + 255) / 256, 256>>>(b1);                  // 6
    gemm2_f16_kernel<<<(N_NODES + 127) / 128, 128, G2_SMEM>>>();           // 7
    int do_lsm = (out_size >= 2 * N_NODES * DOUT) ? 1 : 0;
    agg2_lsm_kernel<<<(N_NODES * 32 + 255) / 256, 256>>>(b2, out, do_lsm); // 8
}

// round 16
// speedup vs baseline: 1.0926x; 1.0926x over previous
#include <cuda_runtime.h>
#include <cuda_fp16.h>
#include <math.h>
#include <stdint.h>

#define N_NODES 100000
#define N_EDGES 1600000
#define DIN 512
#define DH 128
#define DOUT 40
#define TOT_EDGES (N_EDGES + N_NODES)

// ---------------- scratch (device globals; no runtime allocation) -------------
__device__ int      g_degc[N_NODES + 1];  // [i]=deg(+1 after alloc); [N_NODES]=cursor
__device__ int      g_off[N_NODES];       // bucket start (unordered)
__device__ int      g_cur[N_NODES];
__device__ float    g_dinv[N_NODES];
__device__ __align__(16) uint32_t g_csr4[TOT_EDGES];            // (w15 << 17) | src17
__device__ __align__(16) __half g_h1h[(size_t)N_NODES * DH];    // X @ W1 (fp16)
__device__ __align__(16) __half g_a1h[(size_t)N_NODES * DH];    // relu(agg+b1) (fp16)
__device__ __align__(16) __half g_h2h[(size_t)N_NODES * DOUT];  // a1 @ W2 (fp16)
__device__ __align__(16) __half g_w1hf[(size_t)DH * DIN];       // W1 fp16, B-fragment layout
__device__ __align__(16) __half g_w2hf[(size_t)(DH / 16) * DOUT * 16]; // W2 fp16 B-frag

// ---------------- helpers -------------------------------------------------------
__device__ __forceinline__ uint32_t smem_u32(const void* p) {
    uint32_t a;
    asm("{ .reg .u64 t; cvta.to.shared.u64 t, %1; cvt.u32.u64 %0, t; }" : "=r"(a) : "l"(p));
    return a;
}

__device__ __forceinline__ uint32_t packh2(float2 v) {
    __half2 h = __floats2half2_rn(v.x, v.y);
    return *reinterpret_cast<uint32_t*>(&h);
}

// decode packed csr entry -> (src, w)
__device__ __forceinline__ void csr_decode(uint32_t e, int& s, float& w) {
    s = (int)(e & 0x1FFFFu);
    unsigned short hb = (unsigned short)(e >> 17);   // fp16 bits, sign=0
    w = __half2float(__ushort_as_half(hb));
}

__device__ __forceinline__ void mma_f16(float* c, const uint32_t* a, uint32_t b0, uint32_t b1) {
    asm volatile(
        "mma.sync.aligned.m16n8k16.row.col.f32.f16.f16.f32 "
        "{%0,%1,%2,%3}, {%4,%5,%6,%7}, {%8,%9}, {%0,%1,%2,%3};"
        : "+f"(c[0]), "+f"(c[1]), "+f"(c[2]), "+f"(c[3])
        : "r"(a[0]), "r"(a[1]), "r"(a[2]), "r"(a[3]), "r"(b0), "r"(b1));
}

// ---------------- histogram (deg zeroed by one memset; self-loop added in alloc) -
__global__ void hist_kernel(const int* __restrict__ dst) {
    int e = blockIdx.x * blockDim.x + threadIdx.x;
    if (e < N_EDGES) atomicAdd(&g_degc[dst[e]], 1);
}

// ---------------- W precompute (W1 + W2, both fp16 B-fragment layout) ------------
__global__ void wt_kernel(const float* __restrict__ W1, const float* __restrict__ W2) {
    if (blockIdx.y < 16) {
        const int n0 = blockIdx.x * 32, k0 = blockIdx.y * 32;
        const int n = n0 + threadIdx.x, k = k0 + threadIdx.y;
        float v = W1[(size_t)k * DH + n];
        int c = k >> 5, kt = (k >> 4) & 1, q = k & 15;
        size_t slot = ((size_t)(c * 2 + kt) * 128 + n) * 16
                      + ((q & 7) >> 1) * 4 + ((q >> 3) & 1) * 2 + (q & 1);
        g_w1hf[slot] = __float2half_rn(v);
    } else if (blockIdx.x == 0) {
        int tid = threadIdx.y * 32 + threadIdx.x;
        for (int idx = tid; idx < DH * DOUT; idx += 1024) {
            int k = idx / DOUT, n = idx % DOUT;
            int kt = k >> 4, q = k & 15;
            size_t slot = ((size_t)kt * DOUT + n) * 16
                          + ((q & 7) >> 1) * 4 + ((q >> 3) & 1) * 2 + (q & 1);
            g_w2hf[slot] = __float2half_rn(W2[idx]);
        }
    }
}

// ---------------- bucket allocation (order-free CSR); writes total degree back ---
__global__ void alloc_kernel() {
    int i = blockIdx.x * blockDim.x + threadIdx.x;
    if (i >= N_NODES) return;
    int v = g_degc[i] + 1;                // + self-loop
    int off = atomicAdd(&g_degc[N_NODES], v);
    g_degc[i] = v;                        // store total for agg loops
    g_off[i] = off;
    g_cur[i] = off;
    g_dinv[i] = rsqrtf((float)v);
}

__global__ void scatter_kernel(const int* __restrict__ src, const int* __restrict__ dst) {
    int e = blockIdx.x * blockDim.x + threadIdx.x;
    if (e >= TOT_EDGES) return;
    int s, d;
    if (e < N_EDGES) { s = src[e]; d = dst[e]; }
    else             { s = d = e - N_EDGES; }
    int pos = atomicAdd(&g_cur[d], 1);
    float w = g_dinv[s] * g_dinv[d];
    unsigned short hb = __half_as_ushort(__float2half_rn(w));   // sign bit = 0
    g_csr4[pos] = ((uint32_t)hb << 17) | (uint32_t)s;
}

// ---------------- GEMM1: h1 = X @ W1, fp16 MMA (m16n8k16) + 3-stage cp.async -----
#define NCH 16
#define STAGES 3
#define A_STRIDE 40                            // A floats per row (pad 32 -> 40)
#define A_TILE_F (128 * A_STRIDE)              // 5120 floats = 20480 B
#define B_TILE_H 4096                          // fragment-layout fp16 tile (8192 B)
#define STAGE_B (A_TILE_F * 4 + B_TILE_H * 2)  // 28672 B
#define G1_SMEM (STAGES * STAGE_B)             // 86016 B

__global__ __launch_bounds__(256) void gemm1_f16_kernel(const float* __restrict__ X) {
    extern __shared__ float s1[];
    const uint32_t sbase = smem_u32(s1);
    const int tid  = threadIdx.x;
    const int row0 = blockIdx.x * 128;

    const int ldrow = tid >> 3;
    const int ldkq  = tid & 7;

    auto issue = [&](int c) {
        const int s = c % STAGES;
        const uint32_t sa = sbase + s * STAGE_B;
        const uint32_t sb = sa + A_TILE_F * 4;
        const int k0 = c * 32;
        #pragma unroll
        for (int j = 0; j < 4; j++) {
            const int row = ldrow + j * 32;
            const int gr  = row0 + row;
            const int zn  = (gr < N_NODES) ? 16 : 0;
            const float* ga = X + (size_t)(gr < N_NODES ? gr : 0) * DIN + k0 + ldkq * 4;
            asm volatile("cp.async.cg.shared.global [%0], [%1], 16, %2;"
                         :: "r"(sa + row * (A_STRIDE * 4) + ldkq * 16), "l"(ga), "r"(zn));
        }
        const __half* gb = g_w1hf + (size_t)c * B_TILE_H;
        asm volatile("cp.async.cg.shared.global [%0], [%1], 16;"
                     :: "r"(sb + tid * 32), "l"(reinterpret_cast<const char*>(gb) + tid * 32));
        asm volatile("cp.async.cg.shared.global [%0], [%1], 16;"
                     :: "r"(sb + tid * 32 + 16),
                        "l"(reinterpret_cast<const char*>(gb) + tid * 32 + 16));
    };

    issue(0);
    asm volatile("cp.async.commit_group;" ::: "memory");
    issue(1);
    asm volatile("cp.async.commit_group;" ::: "memory");

    const int wid = tid >> 5, lane = tid & 31;
    const int wm = wid & 3, wn = wid >> 2;
    const int g = lane >> 2, tg = lane & 3;

    float acc[2][8][4];
    #pragma unroll
    for (int a = 0; a < 2; a++)
        #pragma unroll
        for (int b = 0; b < 8; b++)
            #pragma unroll
            for (int c = 0; c < 4; c++) acc[a][b][c] = 0.f;

    #pragma unroll 1
    for (int c = 0; c < NCH; c++) {
        asm volatile("cp.async.wait_group 1;" ::: "memory");
        __syncthreads();
        if (c + STAGES - 1 < NCH) issue(c + STAGES - 1);
        asm volatile("cp.async.commit_group;" ::: "memory");

        const float*  sA = s1 + (size_t)(c % STAGES) * (STAGE_B / 4);
        const __half* sB = reinterpret_cast<const __half*>(sA + A_TILE_F);

        #pragma unroll
        for (int kt = 0; kt < 2; kt++) {
            uint32_t a[2][4];
            #pragma unroll
            for (int mt = 0; mt < 2; mt++) {
                const float2* pa = reinterpret_cast<const float2*>(
                    sA + (wm * 32 + mt * 16 + g) * A_STRIDE + kt * 16 + tg * 2);
                const float2* pa8 = pa + 4 * A_STRIDE;   // +8 rows
                float2 v00 = pa[0],  v10 = pa[4];
                float2 v01 = pa8[0], v11 = pa8[4];
                a[mt][0] = packh2(v00);
                a[mt][1] = packh2(v01);
                a[mt][2] = packh2(v10);
                a[mt][3] = packh2(v11);
            }
            #pragma unroll
            for (int nt = 0; nt < 8; nt++) {
                const uint2 b = *reinterpret_cast<const uint2*>(
                    sB + (size_t)kt * 2048 + (wn * 64 + nt * 8 + g) * 16 + tg * 4);
                mma_f16(acc[0][nt], a[0], b.x, b.y);
                mma_f16(acc[1][nt], a[1], b.x, b.y);
            }
        }
    }

    // epilogue -> fp16
    #pragma unroll
    for (int mt = 0; mt < 2; mt++) {
        int r0 = row0 + wm * 32 + mt * 16 + g;
        #pragma unroll
        for (int nt = 0; nt < 8; nt++) {
            int colb = wn * 64 + nt * 8 + tg * 2;
            if (r0 < N_NODES)
                *reinterpret_cast<__half2*>(g_h1h + (size_t)r0 * DH + colb) =
                    __floats2half2_rn(acc[mt][nt][0], acc[mt][nt][1]);
            if (r0 + 8 < N_NODES)
                *reinterpret_cast<__half2*>(g_h1h + (size_t)(r0 + 8) * DH + colb) =
                    __floats2half2_rn(acc[mt][nt][2], acc[mt][nt][3]);
        }
    }
}

// ---------------- Agg1: a1 = relu(A_hat @ h1 + b1), warp per node ----------------
// default (L1-cached) gather: h1 rows re-read ~17x -> exploit 33MB aggregate L1
__global__ void agg1_kernel(const float* __restrict__ b1) {
    int gw = (blockIdx.x * blockDim.x + threadIdx.x) >> 5;
    int lane = threadIdx.x & 31;
    if (gw >= N_NODES) return;
    int beg = g_off[gw], end = beg + g_degc[gw];
    float4 acc = make_float4(0.f, 0.f, 0.f, 0.f);
    for (int p = beg; p < end; ++p) {
        int s; float w;
        csr_decode(g_csr4[p], s, w);
        uint2 hv = *(reinterpret_cast<const uint2*>(g_h1h + (size_t)s * DH) + lane);
        float2 f0 = __half22float2(*reinterpret_cast<__half2*>(&hv.x));
        float2 f1 = __half22float2(*reinterpret_cast<__half2*>(&hv.y));
        acc.x += w * f0.x; acc.y += w * f0.y; acc.z += w * f1.x; acc.w += w * f1.y;
    }
    float4 bv = *reinterpret_cast<const float4*>(b1 + lane * 4);
    __half2 o0 = __floats2half2_rn(fmaxf(acc.x + bv.x, 0.f), fmaxf(acc.y + bv.y, 0.f));
    __half2 o1 = __floats2half2_rn(fmaxf(acc.z + bv.z, 0.f), fmaxf(acc.w + bv.w, 0.f));
    uint2 st;
    st.x = *reinterpret_cast<uint32_t*>(&o0);
    st.y = *reinterpret_cast<uint32_t*>(&o1);
    *(reinterpret_cast<uint2*>(g_a1h + (size_t)gw * DH) + lane) = st;
}

// ---------------- GEMM2: h2 = a1 @ W2 via fp16 MMA (m16n8k16) --------------------
#define G2A_STRIDE_H 136
#define G2_SMEM (128 * G2A_STRIDE_H * 2 + (DH / 16) * DOUT * 16 * 2)
__global__ __launch_bounds__(128) void gemm2_f16_kernel() {
    extern __shared__ __half s2h[];
    __half* sA = s2h;                              // [128][136]
    __half* sB = s2h + 128 * G2A_STRIDE_H;         // fragment layout
    const uint32_t* sA32 = reinterpret_cast<const uint32_t*>(sA);
    const int tid  = threadIdx.x;
    const int row0 = blockIdx.x * 128;

    #pragma unroll
    for (int i = 0; i < 32; i++) {
        int idx = tid + i * 128, row = idx >> 5, q = idx & 31;
        int gr = row0 + row;
        uint2 hv = make_uint2(0u, 0u);
        if (gr < N_NODES)
            hv = __ldcs(reinterpret_cast<const uint2*>(g_a1h + (size_t)gr * DH) + q);
        *reinterpret_cast<uint2*>(sA + row * G2A_STRIDE_H + q * 4) = hv;
    }
    #pragma unroll
    for (int i = 0; i < 5; i++) {
        int idx = tid + i * 128;
        *reinterpret_cast<uint4*>(sB + idx * 8) =
            *reinterpret_cast<const uint4*>(g_w2hf + idx * 8);
    }
    __syncthreads();

    const int wid = tid >> 5, lane = tid & 31;
    const int g = lane >> 2, tg = lane & 3;

    float acc[2][5][4];
    #pragma unroll
    for (int a = 0; a < 2; a++)
        #pragma unroll
        for (int b = 0; b < 5; b++)
            #pragma unroll
            for (int c = 0; c < 4; c++) acc[a][b][c] = 0.f;

    #pragma unroll
    for (int kt = 0; kt < DH / 16; kt++) {
        uint32_t a[2][4];
        #pragma unroll
        for (int mt = 0; mt < 2; mt++) {
            int base = (wid * 32 + mt * 16 + g) * (G2A_STRIDE_H / 2) + kt * 8 + tg;
            a[mt][0] = sA32[base];
            a[mt][1] = sA32[base + 8 * (G2A_STRIDE_H / 2)];
            a[mt][2] = sA32[base + 4];
            a[mt][3] = sA32[base + 8 * (G2A_STRIDE_H / 2) + 4];
        }
        #pragma unroll
        for (int nt = 0; nt < 5; nt++) {
            const uint2 b = *reinterpret_cast<const uint2*>(
                sB + ((size_t)kt * DOUT + nt * 8 + g) * 16 + tg * 4);
            mma_f16(acc[0][nt], a[0], b.x, b.y);
            mma_f16(acc[1][nt], a[1], b.x, b.y);
        }
    }

    #pragma unroll
    for (int mt = 0; mt < 2; mt++) {
        int r0 = row0 + wid * 32 + mt * 16 + g;
        #pragma unroll
        for (int nt = 0; nt < 5; nt++) {
            int colb = nt * 8 + tg * 2;
            if (r0 < N_NODES)
                *reinterpret_cast<__half2*>(g_h2h + (size_t)r0 * DOUT + colb) =
                    __floats2half2_rn(acc[mt][nt][0], acc[mt][nt][1]);
            if (r0 + 8 < N_NODES)
                *reinterpret_cast<__half2*>(g_h2h + (size_t)(r0 + 8) * DOUT + colb) =
                    __floats2half2_rn(acc[mt][nt][2], acc[mt][nt][3]);
        }
    }
}

// ---------------- Agg2 + b2 + log_softmax fused, warp per node -------------------
__device__ __forceinline__ void stcs2(float* p, float2 v) {
    asm volatile("st.global.cs.v2.f32 [%0], {%1, %2};" :: "l"(p), "f"(v.x), "f"(v.y)
                 : "memory");
}

__global__ void agg2_lsm_kernel(const float* __restrict__ b2, float* __restrict__ out,
                                int do_lsm) {
    int gw = (blockIdx.x * blockDim.x + threadIdx.x) >> 5;
    int lane = threadIdx.x & 31;
    if (gw >= N_NODES) return;
    int beg = g_off[gw], end = beg + g_degc[gw];
    const bool act = lane < (DOUT / 2);
    float acc0 = 0.f, acc1 = 0.f;
    for (int p = beg; p < end; ++p) {
        int s; float w;
        csr_decode(g_csr4[p], s, w);
        if (act) {
            uint32_t hv = *(reinterpret_cast<const uint32_t*>(
                g_h2h + (size_t)s * DOUT) + lane);
            float2 f = __half22float2(*reinterpret_cast<__half2*>(&hv));
            acc0 += w * f.x;
            acc1 += w * f.y;
        }
    }
    if (act) {
        acc0 += b2[lane * 2];
        acc1 += b2[lane * 2 + 1];
        stcs2(out + (size_t)gw * DOUT + lane * 2, make_float2(acc0, acc1));
    }
    if (do_lsm) {
        float m = act ? fmaxf(acc0, acc1) : -INFINITY;
        #pragma unroll
        for (int o = 16; o > 0; o >>= 1) m = fmaxf(m, __shfl_xor_sync(0xffffffffu, m, o));
        float e = act ? (expf(acc0 - m) + expf(acc1 - m)) : 0.f;
        #pragma unroll
        for (int o = 16; o > 0; o >>= 1) e += __shfl_xor_sync(0xffffffffu, e, o);
        float lse = m + logf(e);
        if (act) {
            float* lrow = out + (size_t)N_NODES * DOUT + (size_t)gw * DOUT;
            stcs2(lrow + lane * 2, make_float2(acc0 - lse, acc1 - lse));
        }
    }
}

// ---------------- launch --------------------------------------------------------
// chain A (default): wt -> gemm1
// chain B (side):    memset(degc incl cursor) -> hist -> alloc -> scatter
// join -> agg1 -> gemm2 -> agg2_lsm
extern "C" void kernel_launch(void* const* d_in, const int* in_sizes, int n_in,
                              void* d_out, int out_size) {
    const float* x   = (const float*)d_in[0];
    const int*   ei  = (const int*)  d_in[1];   // [2,E] row-major
    const float* W1  = (const float*)d_in[2];
    const float* b1  = (const float*)d_in[3];
    const float* W2  = (const float*)d_in[4];
    const float* b2  = (const float*)d_in[5];
    float* out = (float*)d_out;

    const int* src = ei;
    const int* dst = ei + N_EDGES;

    cudaFuncSetAttribute(gemm1_f16_kernel, cudaFuncAttributeMaxDynamicSharedMemorySize,
                         G1_SMEM);
    cudaFuncSetAttribute(gemm2_f16_kernel, cudaFuncAttributeMaxDynamicSharedMemorySize,
                         G2_SMEM);

    void* degcPtr; cudaGetSymbolAddress(&degcPtr, g_degc);

    cudaStream_t sB;
    cudaStreamCreateWithFlags(&sB, cudaStreamNonBlocking);
    cudaEvent_t evFork, evJoin;
    cudaEventCreateWithFlags(&evFork, cudaEventDisableTiming);
    cudaEventCreateWithFlags(&evJoin, cudaEventDisableTiming);

    cudaEventRecord(evFork, 0);
    cudaStreamWaitEvent(sB, evFork, 0);

    cudaMemsetAsync(degcPtr, 0, (N_NODES + 1) * sizeof(int), sB);

    // kernel submission order: wt(1), hist(2), alloc(3), gemm1(4 <- profile), scatter(5)
    wt_kernel<<<dim3(4, 17), dim3(32, 32)>>>(W1, W2);                      // 1 (A)
    hist_kernel<<<(N_EDGES + 255) / 256, 256, 0, sB>>>(dst);               // 2 (B)
    alloc_kernel<<<(N_NODES + 255) / 256, 256, 0, sB>>>();                 // 3 (B)
    gemm1_f16_kernel<<<(N_NODES + 127) / 128, 256, G1_SMEM>>>(x);          // 4 (A)
    scatter_kernel<<<(TOT_EDGES + 255) / 256, 256, 0, sB>>>(src, dst);     // 5 (B)

    cudaEventRecord(evJoin, sB);
    cudaStreamWaitEvent(0, evJoin, 0);

    agg1_kernel<<<(N_NODES * 32 + 255) / 256, 256>>>(b1);                  // 6
    gemm2_f16_kernel<<<(N_NODES + 127) / 128, 128, G2_SMEM>>>();           // 7
    int do_lsm = (out_size >= 2 * N_NODES * DOUT) ? 1 : 0;
    agg2_lsm_kernel<<<(N_NODES * 32 + 255) / 256, 256>>>(b2, out, do_lsm); // 8
}